// round 1
// baseline (speedup 1.0000x reference)
#include <cuda_runtime.h>
#include <stdint.h>

// ---------------------------------------------------------------------------
// BatchTopK: out = scatter(top_{k*rows}(relu(x).flatten()))
// Exact selection via 2-level radix histogram on float bit patterns.
// ---------------------------------------------------------------------------

#define HB        4096          // histogram bins (12 bits)
#define NPART     512           // private histogram rows (== grid of k_hist1)
#define CAND_CAP  (1u << 20)    // candidate buffer (expected ~94K)
#define C2_CAP    4096          // stage-2 exact-tie buffer (expected ~25)
#define MAIN_BUF  512           // per-block candidate staging

// Scratch (module-static: allowed; no runtime allocation)
__device__ unsigned g_part[NPART * HB];   // 8 MB private histograms
__device__ unsigned g_hist1[HB];
__device__ unsigned g_hist2[HB];
__device__ unsigned g_cand_cnt;
__device__ unsigned g_c2_cnt;
__device__ unsigned g_cand_bits[CAND_CAP];
__device__ int      g_cand_idx [CAND_CAP];
__device__ unsigned g_c2_bits[C2_CAP];
__device__ int      g_c2_idx [C2_CAP];
__device__ int      g_B1;
__device__ unsigned g_cnt_gt1;
__device__ int      g_B2;
__device__ unsigned g_cnt_gt2;
__device__ int      g_keep_all;

static __device__ __forceinline__ long long nkeep_of(const int* kptr, long long n) {
    int k = kptr ? *kptr : 64;
    return (long long)k * (n / 16384);   // num_samples = rows (last dim = 16384)
}

// ---------------------------------------------------------------------------
// K0: zero all accumulators (deterministic across graph replays)
// ---------------------------------------------------------------------------
__global__ void k_zero() {
    int t = blockIdx.x * blockDim.x + threadIdx.x;
    int stride = gridDim.x * blockDim.x;
    for (int i = t; i < HB; i += stride) { g_hist1[i] = 0u; g_hist2[i] = 0u; }
    if (t == 0) { g_cand_cnt = 0u; g_c2_cnt = 0u; g_keep_all = 0; }
}

// ---------------------------------------------------------------------------
// K1: per-block private 4096-bin histogram of top-12 bits of positive floats.
// Positive float  <=>  (int)bits > 0.  Grid MUST be exactly NPART blocks.
// ---------------------------------------------------------------------------
__global__ void k_hist1(const uint4* __restrict__ x4, long long n4) {
    __shared__ unsigned sh[HB];
    for (int i = threadIdx.x; i < HB; i += blockDim.x) sh[i] = 0u;
    __syncthreads();

    long long stride = (long long)gridDim.x * blockDim.x;
    for (long long i = (long long)blockIdx.x * blockDim.x + threadIdx.x; i < n4; i += stride) {
        uint4 v = x4[i];
        if ((int)v.x > 0) atomicAdd(&sh[v.x >> 20], 1u);
        if ((int)v.y > 0) atomicAdd(&sh[v.y >> 20], 1u);
        if ((int)v.z > 0) atomicAdd(&sh[v.z >> 20], 1u);
        if ((int)v.w > 0) atomicAdd(&sh[v.w >> 20], 1u);
    }
    __syncthreads();
    unsigned* row = &g_part[(long long)blockIdx.x * HB];
    for (int i = threadIdx.x; i < HB; i += blockDim.x) row[i] = sh[i];
}

// ---------------------------------------------------------------------------
// K_red: sum NPART private rows -> g_hist1.  Thread t: bin t&(HB-1),
// row-chunk t>>12 (4 chunks of 128 rows).  Launch <<<64,256>>>.
// ---------------------------------------------------------------------------
__global__ void k_red() {
    int t = blockIdx.x * blockDim.x + threadIdx.x;   // 16384 threads
    int b = t & (HB - 1);
    int c = t >> 12;                                  // 0..3
    unsigned s = 0u;
    #pragma unroll 8
    for (int r = c * 128; r < (c + 1) * 128; r++)
        s += g_part[(long long)r * HB + b];
    if (s) atomicAdd(&g_hist1[b], s);
}

// ---------------------------------------------------------------------------
// Suffix-scan a 4096-bin histogram (1 block, 1024 threads, 4 bins/thread).
// Finds B: prior+cumGE[B] >= n_keep > prior+cumGE[B+1].
// ---------------------------------------------------------------------------
static __device__ void scan_core(const unsigned* __restrict__ hist, unsigned prior,
                                 long long n_keep, int* outB, unsigned* outCnt,
                                 int stage1) {
    __shared__ unsigned ssum[1024];
    int t = threadIdx.x;
    unsigned h[4];
    #pragma unroll
    for (int j = 0; j < 4; j++) h[j] = hist[4 * t + j];
    unsigned local = h[0] + h[1] + h[2] + h[3];
    ssum[t] = local;
    __syncthreads();
    for (int off = 1; off < 1024; off <<= 1) {
        unsigned v = (t + off < 1024) ? ssum[t + off] : 0u;
        __syncthreads();
        ssum[t] += v;
        __syncthreads();
    }
    unsigned excl = ssum[t] - local;                 // sum over threads > t
    if (t == 0) {
        long long total = (long long)ssum[0] + prior;
        if (total < n_keep) {                         // keep everything
            *outB = -1; *outCnt = prior;
            if (stage1) g_keep_all = 1;
        }
    }
    unsigned c3 = excl + h[3], c2 = c3 + h[2], c1 = c2 + h[1], c0 = c1 + h[0];
    unsigned cg[4] = {c0, c1, c2, c3};
    unsigned cn[4] = {c1, c2, c3, excl};
    #pragma unroll
    for (int j = 0; j < 4; j++) {
        long long tot = (long long)prior + cg[j];
        long long nxt = (long long)prior + cn[j];
        if (tot >= n_keep && nxt < n_keep) {          // unique crossing
            *outB = 4 * t + j;
            *outCnt = (unsigned)nxt;
        }
    }
}

__global__ void k_scan1(const int* kptr, long long n) {
    scan_core(g_hist1, 0u, nkeep_of(kptr, n), &g_B1, &g_cnt_gt1, 1);
}
__global__ void k_scan2(const int* kptr, long long n) {
    scan_core(g_hist2, g_cnt_gt1, nkeep_of(kptr, n), &g_B2, &g_cnt_gt2, 0);
}

// ---------------------------------------------------------------------------
// K3: main pass.  out = x if key12 > B1 else 0; key12 == B1 -> candidate.
// Block-aggregated candidate append (1 global atomic / block).
// ---------------------------------------------------------------------------
static __device__ __forceinline__ unsigned proc_elem(unsigned b, int idx, int B1,
                                                     unsigned* s_cnt,
                                                     unsigned* s_bits, int* s_idx) {
    if ((int)b <= 0) return 0u;                  // relu: non-positive -> 0
    int key = (int)(b >> 20);
    if (key > B1) return b;                      // definitely kept
    if (key == B1) {                             // boundary bin -> candidate
        unsigned p = atomicAdd(s_cnt, 1u);
        if (p < MAIN_BUF) { s_bits[p] = b; s_idx[p] = idx; }
    }
    return 0u;
}

__global__ void k_main(const uint4* __restrict__ x4, uint4* __restrict__ o4,
                       long long n4) {
    __shared__ unsigned s_cnt;
    __shared__ unsigned s_base;
    __shared__ unsigned s_bits[MAIN_BUF];
    __shared__ int      s_idx [MAIN_BUF];
    if (threadIdx.x == 0) s_cnt = 0u;
    __syncthreads();

    int B1 = g_B1;                                // -1 in keep_all case -> pass-through
    long long stride = (long long)gridDim.x * blockDim.x;
    for (long long i = (long long)blockIdx.x * blockDim.x + threadIdx.x; i < n4; i += stride) {
        uint4 v = x4[i];
        int base = (int)(4 * i);
        uint4 o;
        o.x = proc_elem(v.x, base + 0, B1, &s_cnt, s_bits, s_idx);
        o.y = proc_elem(v.y, base + 1, B1, &s_cnt, s_bits, s_idx);
        o.z = proc_elem(v.z, base + 2, B1, &s_cnt, s_bits, s_idx);
        o.w = proc_elem(v.w, base + 3, B1, &s_cnt, s_bits, s_idx);
        o4[i] = o;
    }
    __syncthreads();
    unsigned nm = s_cnt < MAIN_BUF ? s_cnt : MAIN_BUF;
    if (threadIdx.x == 0) s_base = atomicAdd(&g_cand_cnt, nm);
    __syncthreads();
    for (unsigned i = threadIdx.x; i < nm; i += blockDim.x) {
        unsigned p = s_base + i;
        if (p < CAND_CAP) { g_cand_bits[p] = s_bits[i]; g_cand_idx[p] = s_idx[i]; }
    }
}

// ---------------------------------------------------------------------------
// K4: histogram candidates on bits[19:8] (next 12 bits).
// ---------------------------------------------------------------------------
__global__ void k_hist2() {
    unsigned n = g_cand_cnt; if (n > CAND_CAP) n = CAND_CAP;
    unsigned stride = gridDim.x * blockDim.x;
    for (unsigned i = blockIdx.x * blockDim.x + threadIdx.x; i < n; i += stride)
        atomicAdd(&g_hist2[(g_cand_bits[i] >> 8) & 0xFFFu], 1u);
}

// ---------------------------------------------------------------------------
// K6: scatter candidates above B2; exact sub-bin -> c2 buffer.
// ---------------------------------------------------------------------------
__global__ void k_scatter(float* __restrict__ out) {
    int B2 = g_B2;
    unsigned n = g_cand_cnt; if (n > CAND_CAP) n = CAND_CAP;
    unsigned stride = gridDim.x * blockDim.x;
    for (unsigned i = blockIdx.x * blockDim.x + threadIdx.x; i < n; i += stride) {
        unsigned b = g_cand_bits[i];
        int key = (int)((b >> 8) & 0xFFFu);
        if (key > B2) {
            out[g_cand_idx[i]] = __uint_as_float(b);
        } else if (key == B2) {
            unsigned p = atomicAdd(&g_c2_cnt, 1u);
            if (p < C2_CAP) { g_c2_bits[p] = b; g_c2_idx[p] = g_cand_idx[i]; }
        }
    }
}

// ---------------------------------------------------------------------------
// K7: exact finish. Sort (bits desc, idx asc) the few survivors; write the
// first `need` — exact jax top_k tie semantics.
// ---------------------------------------------------------------------------
__global__ void k_final(float* __restrict__ out, const int* kptr, long long n) {
    __shared__ unsigned long long keys[C2_CAP];
    int t = threadIdx.x;
    long long n_keep = nkeep_of(kptr, n);
    long long need = n_keep - (long long)g_cnt_gt2;
    unsigned m = g_c2_cnt; if (m > C2_CAP) m = C2_CAP;
    if (need <= 0 || m == 0) return;

    for (int i = t; i < C2_CAP; i += blockDim.x) {
        if ((unsigned)i < m)
            keys[i] = ((unsigned long long)g_c2_bits[i] << 32)
                    | (unsigned)(~(unsigned)g_c2_idx[i]);   // ties: lower idx first
        else
            keys[i] = 0ull;
    }
    __syncthreads();
    // bitonic sort, descending
    for (unsigned kk = 2; kk <= C2_CAP; kk <<= 1) {
        for (unsigned j = kk >> 1; j > 0; j >>= 1) {
            for (unsigned i = t; i < C2_CAP; i += blockDim.x) {
                unsigned ixj = i ^ j;
                if (ixj > i) {
                    bool desc = ((i & kk) == 0);
                    unsigned long long a = keys[i], b = keys[ixj];
                    if ((a < b) == desc) { keys[i] = b; keys[ixj] = a; }
                }
            }
            __syncthreads();
        }
    }
    if (need > (long long)m) need = m;
    for (long long i = t; i < need; i += blockDim.x) {
        unsigned long long kv = keys[i];
        unsigned bits = (unsigned)(kv >> 32);
        int idx = (int)(~(unsigned)(kv & 0xFFFFFFFFull));
        out[idx] = __uint_as_float(bits);
    }
}

// ---------------------------------------------------------------------------
extern "C" void kernel_launch(void* const* d_in, const int* in_sizes, int n_in,
                              void* d_out, int out_size) {
    const float* x = (const float*)d_in[0];
    const int* kptr = (n_in > 1) ? (const int*)d_in[1] : nullptr;
    long long n  = (long long)in_sizes[0];
    long long n4 = n / 4;
    const uint4* x4 = (const uint4*)x;
    uint4* o4 = (uint4*)d_out;
    float* out = (float*)d_out;

    k_zero   <<<8,   1024>>>();
    k_hist1  <<<NPART, 256>>>(x4, n4);
    k_red    <<<64,  256>>>();
    k_scan1  <<<1,  1024>>>(kptr, n);
    k_main   <<<2048, 256>>>(x4, o4, n4);
    k_hist2  <<<256, 256>>>();
    k_scan2  <<<1,  1024>>>(kptr, n);
    k_scatter<<<256, 256>>>(out);
    k_final  <<<1,  1024>>>(out, kptr, n);
    (void)out_size;
}

// round 2
// speedup vs baseline: 1.3189x; 1.3189x over previous
#include <cuda_runtime.h>
#include <stdint.h>

// ---------------------------------------------------------------------------
// BatchTopK: out = scatter(top_{k*rows}(relu(x).flatten()))
// Exact 2-level radix select on float bit patterns.
//   Stage 1: 4096-bin hist of bits[31:20], restricted to values >= 0.5
//            (below-cut positives counted exactly; flag-gated exact fallback).
//   Stage 2: sub-histogram of bits[19:8] built inline during the output pass.
//   Stage 3: exact tie-break (bits desc, idx asc) on ~dozens of survivors.
// ---------------------------------------------------------------------------

#define HB        4096
#define CUT_KEY   0x3F0u        // (0.5f bits) >> 20
#define CAND_CAP  (1u << 20)
#define C2_CAP    4096
#define MAIN_BUF  1024

__device__ unsigned g_hist1[HB];
__device__ unsigned g_hist2[HB];
__device__ unsigned g_low;        // positives with key < CUT_KEY (exact count)
__device__ int      g_flag;       // 1 => boundary below cut; fallback path
__device__ unsigned g_cand_cnt;
__device__ unsigned g_c2_cnt;
__device__ unsigned g_cand_bits[CAND_CAP];
__device__ int      g_cand_idx [CAND_CAP];
__device__ unsigned g_c2_bits[C2_CAP];
__device__ int      g_c2_idx [C2_CAP];
__device__ int      g_B1;
__device__ unsigned g_cnt_gt1;
__device__ int      g_B2;
__device__ unsigned g_cnt_gt2;

static __device__ __forceinline__ long long nkeep_of(const int* kptr, long long n) {
    int k = kptr ? *kptr : 64;
    return (long long)k * (n / 16384);
}

// ---------------------------------------------------------------------------
__global__ void k_zero() {
    int t = blockIdx.x * blockDim.x + threadIdx.x;   // 4096 threads
    if (t < HB) g_hist1[t] = 0u;
    if (t == 0) { g_low = 0u; g_flag = 0; }
}

// ---------------------------------------------------------------------------
// K1: shared 4096-bin hist of top-12 bits, only for values >= 0.5.
// Below-cut positives -> register count -> 1 global atomic per block.
// Flush only nonzero bins (few dozen) via global atomics.
// ---------------------------------------------------------------------------
__global__ void k_hist1(const uint4* __restrict__ x4, long long n4) {
    __shared__ unsigned sh[HB];
    __shared__ unsigned slow;
    for (int i = threadIdx.x; i < HB; i += blockDim.x) sh[i] = 0u;
    if (threadIdx.x == 0) slow = 0u;
    __syncthreads();

    unsigned low = 0u;
    long long stride = (long long)gridDim.x * blockDim.x;
    for (long long i = (long long)blockIdx.x * blockDim.x + threadIdx.x; i < n4; i += stride) {
        uint4 v = x4[i];
        #pragma unroll
        for (int j = 0; j < 4; j++) {
            unsigned b = (j == 0) ? v.x : (j == 1) ? v.y : (j == 2) ? v.z : v.w;
            if ((int)b > 0) {
                unsigned key = b >> 20;
                if (key >= CUT_KEY) atomicAdd(&sh[key], 1u);
                else                low++;
            }
        }
    }
    // reduce low: warp shuffle -> shared -> global
    #pragma unroll
    for (int off = 16; off > 0; off >>= 1) low += __shfl_down_sync(~0u, low, off);
    if ((threadIdx.x & 31) == 0 && low) atomicAdd(&slow, low);
    __syncthreads();
    if (threadIdx.x == 0 && slow) atomicAdd(&g_low, slow);
    for (int i = threadIdx.x; i < HB; i += blockDim.x) {
        unsigned s = sh[i];
        if (s) atomicAdd(&g_hist1[i], s);
    }
}

// ---------------------------------------------------------------------------
// Suffix scan of a 4096-bin histogram (1 block / 1024 threads, shuffle-based).
// mode 1: stage-1 (cut-aware: may set keep-all or g_flag)
// mode 0: plain (keep-all -> B=-1, cnt=prior)
// ---------------------------------------------------------------------------
static __device__ void scan_core(const unsigned* __restrict__ hist, unsigned prior,
                                 long long n_keep, int* outB, unsigned* outCnt,
                                 int mode) {
    __shared__ unsigned wsuf[32];
    __shared__ unsigned total_sh;
    int t = threadIdx.x, lane = t & 31, w = t >> 5;
    unsigned h[4];
    #pragma unroll
    for (int j = 0; j < 4; j++) h[j] = hist[4 * t + j];
    unsigned local = h[0] + h[1] + h[2] + h[3];

    // inclusive suffix within warp (sum over lanes >= lane)
    unsigned s = local;
    #pragma unroll
    for (int off = 1; off < 32; off <<= 1) {
        unsigned v = __shfl_down_sync(~0u, s, off);
        if (lane + off < 32) s += v;
    }
    if (lane == 0) wsuf[w] = s;          // warp totals (temporarily)
    __syncthreads();
    if (w == 0) {
        unsigned ws = wsuf[lane];
        unsigned tsuf = ws;
        #pragma unroll
        for (int off = 1; off < 32; off <<= 1) {
            unsigned v = __shfl_down_sync(~0u, tsuf, off);
            if (lane + off < 32) tsuf += v;
        }
        unsigned excl = __shfl_down_sync(~0u, tsuf, 1);   // sum over warps > lane
        if (lane == 31) excl = 0u;
        if (lane == 0) total_sh = tsuf;
        wsuf[lane] = excl;
    }
    __syncthreads();

    unsigned S = wsuf[w] + s;            // cumGE(bin 4t) inclusive to end
    unsigned pre = 0u;
    #pragma unroll
    for (int j = 0; j < 4; j++) {
        unsigned cg = S - pre;           // cumGE(4t+j)
        unsigned cn = cg - h[j];         // cumGE(4t+j+1)
        long long tot = (long long)prior + cg;
        long long nxt = (long long)prior + cn;
        if (h[j] && tot >= n_keep && nxt < n_keep) {
            *outB = 4 * t + j;
            *outCnt = (unsigned)nxt;
        }
        pre += h[j];
    }
    if (t == 0) {
        long long totalHist = (long long)prior + total_sh;
        if (mode == 1) {
            long long totalAll = totalHist + g_low;
            if (n_keep >= totalAll) { *outB = -1; *outCnt = 0u; }      // keep-all
            else if (n_keep > totalHist) g_flag = 1;                    // fallback
        } else {
            if (n_keep > totalHist) { *outB = -1; *outCnt = prior; }
        }
    }
}

__global__ void k_scan1(const int* kptr, long long n) {
    // zero stage-2 scratch (used only by later kernels)
    int t = threadIdx.x;
    #pragma unroll
    for (int j = 0; j < 4; j++) g_hist2[4 * t + j] = 0u;
    if (t == 0) { g_cand_cnt = 0u; g_c2_cnt = 0u; }
    __syncthreads();
    scan_core(g_hist1, 0u, nkeep_of(kptr, n), &g_B1, &g_cnt_gt1, 1);
}

// Flag-gated exact fallback: complete the histogram below the cut.
__global__ void k_histfb(const uint4* __restrict__ x4, long long n4) {
    if (!g_flag) return;
    __shared__ unsigned sh[HB];
    for (int i = threadIdx.x; i < HB; i += blockDim.x) sh[i] = 0u;
    __syncthreads();
    long long stride = (long long)gridDim.x * blockDim.x;
    for (long long i = (long long)blockIdx.x * blockDim.x + threadIdx.x; i < n4; i += stride) {
        uint4 v = x4[i];
        #pragma unroll
        for (int j = 0; j < 4; j++) {
            unsigned b = (j == 0) ? v.x : (j == 1) ? v.y : (j == 2) ? v.z : v.w;
            if ((int)b > 0) {
                unsigned key = b >> 20;
                if (key < CUT_KEY) atomicAdd(&sh[key], 1u);
            }
        }
    }
    __syncthreads();
    for (int i = threadIdx.x; i < HB; i += blockDim.x) {
        unsigned s = sh[i];
        if (s) atomicAdd(&g_hist1[i], s);
    }
}

__global__ void k_scan1b(const int* kptr, long long n) {
    if (!g_flag) return;
    scan_core(g_hist1, 0u, nkeep_of(kptr, n), &g_B1, &g_cnt_gt1, 0);
}

// ---------------------------------------------------------------------------
// Main pass: out = x if key > B1 else 0; key == B1 -> candidate + inline hist2.
// ---------------------------------------------------------------------------
static __device__ __forceinline__ unsigned proc_elem(unsigned b, int idx, int B1,
                                                     unsigned* s_cnt,
                                                     unsigned* s_bits, int* s_idx) {
    if ((int)b <= 0) return 0u;
    int key = (int)(b >> 20);
    if (key > B1) return b;
    if (key == B1) {
        atomicAdd(&g_hist2[(b >> 8) & 0xFFFu], 1u);
        unsigned p = atomicAdd(s_cnt, 1u);
        if (p < MAIN_BUF) { s_bits[p] = b; s_idx[p] = idx; }
    }
    return 0u;
}

__global__ void k_main(const uint4* __restrict__ x4, uint4* __restrict__ o4,
                       long long n4) {
    __shared__ unsigned s_cnt, s_base;
    __shared__ unsigned s_bits[MAIN_BUF];
    __shared__ int      s_idx [MAIN_BUF];
    if (threadIdx.x == 0) s_cnt = 0u;
    __syncthreads();

    int B1 = g_B1;
    long long stride = (long long)gridDim.x * blockDim.x;
    for (long long i = (long long)blockIdx.x * blockDim.x + threadIdx.x; i < n4; i += stride) {
        uint4 v = x4[i];
        int base = (int)(4 * i);
        uint4 o;
        o.x = proc_elem(v.x, base + 0, B1, &s_cnt, s_bits, s_idx);
        o.y = proc_elem(v.y, base + 1, B1, &s_cnt, s_bits, s_idx);
        o.z = proc_elem(v.z, base + 2, B1, &s_cnt, s_bits, s_idx);
        o.w = proc_elem(v.w, base + 3, B1, &s_cnt, s_bits, s_idx);
        o4[i] = o;
    }
    __syncthreads();
    unsigned nm = s_cnt < MAIN_BUF ? s_cnt : MAIN_BUF;
    if (threadIdx.x == 0) s_base = atomicAdd(&g_cand_cnt, nm);
    __syncthreads();
    for (unsigned i = threadIdx.x; i < nm; i += blockDim.x) {
        unsigned p = s_base + i;
        if (p < CAND_CAP) { g_cand_bits[p] = s_bits[i]; g_cand_idx[p] = s_idx[i]; }
    }
}

__global__ void k_scan2(const int* kptr, long long n) {
    scan_core(g_hist2, g_cnt_gt1, nkeep_of(kptr, n), &g_B2, &g_cnt_gt2, 0);
}

// ---------------------------------------------------------------------------
__global__ void k_scatter(float* __restrict__ out) {
    int B2 = g_B2;
    unsigned n = g_cand_cnt; if (n > CAND_CAP) n = CAND_CAP;
    unsigned stride = gridDim.x * blockDim.x;
    for (unsigned i = blockIdx.x * blockDim.x + threadIdx.x; i < n; i += stride) {
        unsigned b = g_cand_bits[i];
        int key = (int)((b >> 8) & 0xFFFu);
        if (key > B2) {
            out[g_cand_idx[i]] = __uint_as_float(b);
        } else if (key == B2) {
            unsigned p = atomicAdd(&g_c2_cnt, 1u);
            if (p < C2_CAP) { g_c2_bits[p] = b; g_c2_idx[p] = g_cand_idx[i]; }
        }
    }
}

// ---------------------------------------------------------------------------
// Exact finish: sort survivors by (bits desc, idx asc), write first `need`.
// ---------------------------------------------------------------------------
__global__ void k_final(float* __restrict__ out, const int* kptr, long long n) {
    __shared__ unsigned long long keys[C2_CAP];
    int t = threadIdx.x;
    long long n_keep = nkeep_of(kptr, n);
    long long need = n_keep - (long long)g_cnt_gt2;
    unsigned m = g_c2_cnt; if (m > C2_CAP) m = C2_CAP;
    if (need <= 0 || m == 0) return;

    unsigned n2 = 2;
    while (n2 < m) n2 <<= 1;

    for (unsigned i = t; i < n2; i += blockDim.x)
        keys[i] = (i < m)
            ? ((unsigned long long)g_c2_bits[i] << 32) | (unsigned)(~(unsigned)g_c2_idx[i])
            : 0ull;
    __syncthreads();
    for (unsigned kk = 2; kk <= n2; kk <<= 1) {
        for (unsigned j = kk >> 1; j > 0; j >>= 1) {
            for (unsigned i = t; i < n2; i += blockDim.x) {
                unsigned ixj = i ^ j;
                if (ixj > i) {
                    bool desc = ((i & kk) == 0);
                    unsigned long long a = keys[i], b = keys[ixj];
                    if ((a < b) == desc) { keys[i] = b; keys[ixj] = a; }
                }
            }
            __syncthreads();
        }
    }
    if (need > (long long)m) need = m;
    for (long long i = t; i < need; i += blockDim.x) {
        unsigned long long kv = keys[i];
        unsigned bits = (unsigned)(kv >> 32);
        int idx = (int)(~(unsigned)(kv & 0xFFFFFFFFull));
        out[idx] = __uint_as_float(bits);
    }
}

// ---------------------------------------------------------------------------
extern "C" void kernel_launch(void* const* d_in, const int* in_sizes, int n_in,
                              void* d_out, int out_size) {
    const float* x = (const float*)d_in[0];
    const int* kptr = (n_in > 1) ? (const int*)d_in[1] : nullptr;
    long long n  = (long long)in_sizes[0];
    long long n4 = n / 4;
    const uint4* x4 = (const uint4*)x;
    uint4* o4 = (uint4*)d_out;
    float* out = (float*)d_out;

    k_zero   <<<4,    1024>>>();
    k_hist1  <<<2048, 256>>>(x4, n4);
    k_scan1  <<<1,    1024>>>(kptr, n);
    k_histfb <<<2048, 256>>>(x4, n4);
    k_scan1b <<<1,    1024>>>(kptr, n);
    k_main   <<<2048, 256>>>(x4, o4, n4);
    k_scan2  <<<1,    1024>>>(kptr, n);
    k_scatter<<<256,  256>>>(out);
    k_final  <<<1,    1024>>>(out, kptr, n);
    (void)out_size;
}